// round 3
// baseline (speedup 1.0000x reference)
#include <cuda_runtime.h>
#include <math.h>

#define GS_MAX   96
#define MAXOUT   49152       // 3*128*128
#define RPB      8           // rows per block (processed as 4 f32x2 pairs)

__device__ float d_partial[GS_MAX * MAXOUT];   // per-chunk partial images

typedef unsigned long long u64;

// ---- f32x2 packed helpers (Blackwell packed-fp32 path, PTX-only) ----------
__device__ __forceinline__ u64 pk(float lo, float hi) {
    u64 r; asm("mov.b64 %0,{%1,%2};" : "=l"(r) : "f"(lo), "f"(hi)); return r;
}
__device__ __forceinline__ void unpk(u64 v, float& lo, float& hi) {
    asm("mov.b64 {%0,%1},%2;" : "=f"(lo), "=f"(hi) : "l"(v));
}
__device__ __forceinline__ u64 fma2(u64 a, u64 b, u64 c) {
    u64 d; asm("fma.rn.f32x2 %0,%1,%2,%3;" : "=l"(d) : "l"(a), "l"(b), "l"(c)); return d;
}
__device__ __forceinline__ u64 mul2(u64 a, u64 b) {
    u64 d; asm("mul.rn.f32x2 %0,%1,%2;" : "=l"(d) : "l"(a), "l"(b)); return d;
}
__device__ __forceinline__ float ex2n(float t) {   // 2^-t  (neg folds into MUFU modifier)
    float r, nt = -t;
    asm("ex2.approx.ftz.f32 %0,%1;" : "=f"(r) : "f"(nt));
    return r;
}

// ---------------------------------------------------------------------------
// Fused prep + splat.
// Block = (row strip of RPB rows) x (gaussian chunk).  threadIdx.x = column.
// Prep (rotation/scale/center/alpha folding) is computed per block for its
// own <=128 gaussians directly into shared memory — no separate kernel.
//
// u' = px*m00 + py*m01 + bu ; v' = px*m10 + py*m11 + bv, rows prescaled by
// SF = sqrt(0.5*log2(e)) so weight = 2^-(u'^2 + v'^2).
// ---------------------------------------------------------------------------
__global__ void __launch_bounds__(128, 8)
splat_kernel(const float* __restrict__ pos,
             const float* __restrict__ colr,
             const float* __restrict__ lsc,
             const float* __restrict__ rot,
             const float* __restrict__ alph,
             const int*   __restrict__ pnum,
             int N, int H, int W, int chunkSize, int HW)
{
    __shared__ ulonglong2 sM[128];   // {m01|m01 , m11|m11}
    __shared__ ulonglong2 sC[128];   // {cr|cr   , cg|cg}
    __shared__ u64        sB[128];   // cb|cb
    __shared__ float4     sS[128];   // {m00, m10, bu, bv}

    const int colx    = threadIdx.x;            // blockDim.x == W (128)
    const int rowBase = blockIdx.x * RPB;
    const int chunk   = blockIdx.y;
    const int na      = pnum ? *pnum : N;

    const float px = -1.0f + 2.0f * colx / (float)(W - 1);

    u64 py2[RPB / 2];
#pragma unroll
    for (int p = 0; p < RPB / 2; p++) {
        int r0 = rowBase + 2 * p;     if (r0 > H - 1) r0 = H - 1;
        int r1 = rowBase + 2 * p + 1; if (r1 > H - 1) r1 = H - 1;
        float y0 = -1.0f + 2.0f * r0 / (float)(H - 1);
        float y1 = -1.0f + 2.0f * r1 / (float)(H - 1);
        py2[p] = pk(y0, y1);
    }

    u64 aR[RPB / 2], aG[RPB / 2], aB[RPB / 2];
#pragma unroll
    for (int p = 0; p < RPB / 2; p++) { aR[p] = 0ull; aG[p] = 0ull; aB[p] = 0ull; }

    const int g0 = chunk * chunkSize;
    int g1 = g0 + chunkSize; if (g1 > N) g1 = N;

    for (int gbase = g0; gbase < g1; gbase += 128) {
        // ---- fused prep into shared -------------------------------------
        int idx = gbase + threadIdx.x;
        if (threadIdx.x < 128) {
            if (idx < g1) {
                float gx = pos[2 * idx], gy = pos[2 * idx + 1];
                float sx = expf(lsc[2 * idx])     + 1e-6f;
                float sy = expf(lsc[2 * idx + 1]) + 1e-6f;
                float rr = rot[idx];
                float c  = cosf(rr), s = sinf(rr);
                const float SF = 0.8493218002880191f;   // sqrt(0.5*log2(e))
                float isx = SF / sx, isy = SF / sy;
                float m00 =  c * isx, m01 = s * isx;
                float m10 = -s * isy, m11 = c * isy;
                float bu  = -(gx * m00 + gy * m01);
                float bv  = -(gx * m10 + gy * m11);
                float a   = (idx < na) ? alph[idx] : 0.0f;
                float cr  = a * colr[3 * idx];
                float cg  = a * colr[3 * idx + 1];
                float cb  = a * colr[3 * idx + 2];
                sM[threadIdx.x] = make_ulonglong2(pk(m01, m01), pk(m11, m11));
                sC[threadIdx.x] = make_ulonglong2(pk(cr, cr),  pk(cg, cg));
                sB[threadIdx.x] = pk(cb, cb);
                sS[threadIdx.x] = make_float4(m00, m10, bu, bv);
            } else {
                sM[threadIdx.x] = make_ulonglong2(0ull, 0ull);
                sC[threadIdx.x] = make_ulonglong2(0ull, 0ull);
                sB[threadIdx.x] = 0ull;
                sS[threadIdx.x] = make_float4(0.f, 0.f, 0.f, 0.f);
            }
        }
        __syncthreads();

        int cnt = g1 - gbase; if (cnt > 128) cnt = 128;
#pragma unroll 2
        for (int j = 0; j < cnt; j++) {
            ulonglong2 M  = sM[j];
            ulonglong2 C  = sC[j];
            u64        cb = sB[j];
            float4     S  = sS[j];
            float cu = fmaf(px, S.x, S.z);
            float cv = fmaf(px, S.y, S.w);
            u64 cuu = pk(cu, cu);
            u64 cvv = pk(cv, cv);
#pragma unroll
            for (int p = 0; p < RPB / 2; p++) {
                u64 u  = fma2(py2[p], M.x, cuu);
                u64 v  = fma2(py2[p], M.y, cvv);
                u64 uu = mul2(u, u);
                u64 t  = fma2(v, v, uu);
                float t0, t1; unpk(t, t0, t1);
                float e0 = ex2n(t0);
                float e1 = ex2n(t1);
                u64 e01 = pk(e0, e1);
                aR[p] = fma2(e01, C.x, aR[p]);
                aG[p] = fma2(e01, C.y, aG[p]);
                aB[p] = fma2(e01, cb,  aB[p]);
            }
        }
        __syncthreads();
    }

    // deterministic per-chunk partials
    float* base = d_partial + (size_t)chunk * 3 * HW;
#pragma unroll
    for (int p = 0; p < RPB / 2; p++) {
        float r0, r1, g0v, g1v, b0, b1;
        unpk(aR[p], r0, r1);
        unpk(aG[p], g0v, g1v);
        unpk(aB[p], b0, b1);
        int row0 = rowBase + 2 * p;
        int row1 = rowBase + 2 * p + 1;
        if (row0 < H) {
            int pix = row0 * W + colx;
            base[0 * HW + pix] = r0; base[1 * HW + pix] = g0v; base[2 * HW + pix] = b0;
        }
        if (row1 < H) {
            int pix = row1 * W + colx;
            base[0 * HW + pix] = r1; base[1 * HW + pix] = g1v; base[2 * HW + pix] = b1;
        }
    }
}

// ---------------------------------------------------------------------------
// Reduce GS partials (L2-resident), subtract 1. Vectorized float4.
// ---------------------------------------------------------------------------
__global__ void reduce_kernel(float4* __restrict__ out, int total4, int gs)
{
    int i = blockIdx.x * blockDim.x + threadIdx.x;
    if (i >= total4) return;
    float4 s = make_float4(-1.f, -1.f, -1.f, -1.f);
    const float4* part = (const float4*)d_partial;
    for (int k = 0; k < gs; k++) {
        float4 p = part[(size_t)k * total4 + i];
        s.x += p.x; s.y += p.y; s.z += p.z; s.w += p.w;
    }
    out[i] = s;
}

extern "C" void kernel_launch(void* const* d_in, const int* in_sizes, int n_in,
                              void* d_out, int out_size)
{
    const float* pos  = (const float*)d_in[0];   // [1,N,2]
    const float* col  = (const float*)d_in[1];   // [1,N,3]
    const float* lsc  = (const float*)d_in[2];   // [1,N,2]
    const float* rot  = (const float*)d_in[3];   // [1,N]
    const float* alph = (const float*)d_in[4];   // [1,N]
    const int*   pnum = (n_in > 7) ? (const int*)d_in[7] : nullptr;

    int N  = in_sizes[0] / 2;
    int HW = out_size / 3;
    int W  = (int)(sqrt((double)HW) + 0.5);
    int H  = HW / W;
    float* out = (float*)d_out;

    int strips = (H + RPB - 1) / RPB;                    // 16 for H=128
    int GS = 1184 / strips;                              // target 8 CTAs/SM wave
    if (GS < 1) GS = 1;
    if (GS > GS_MAX) GS = GS_MAX;
    if (GS > N) GS = N;
    int chunkSize = (N + GS - 1) / GS;                   // 56 for N=4096,GS=74

    dim3 grid(strips, GS);
    splat_kernel<<<grid, W>>>(pos, col, lsc, rot, alph, pnum,
                              N, H, W, chunkSize, HW);

    int total4 = out_size / 4;
    reduce_kernel<<<(total4 + 255) / 256, 256>>>((float4*)out, total4, GS);
}

// round 4
// speedup vs baseline: 1.3914x; 1.3914x over previous
#include <cuda_runtime.h>
#include <math.h>

#define MAXN     16384
#define TCAP     64          // max tiles (8x8 for 128x128, 16px tiles)
#define CHUNKS   18          // chunks per tile -> 64*18 = 1152 blocks
#define MAXOUT   49152       // 3*128*128

// per-gaussian precomputed params
__device__ float4 d_gA[MAXN];                    // {m00, m01, m10, m11} (prescaled)
__device__ float4 d_gB[MAXN];                    // {bu, bv, cr, cg}
__device__ float  d_gC[MAXN];                    // cb
__device__ float4 d_gP[MAXN];                    // {gx, gy, rmax2, 0}
__device__ int    d_list[TCAP * MAXN];           // per-tile gaussian index lists
__device__ int    d_count[TCAP];
__device__ float  d_partial[CHUNKS * MAXOUT];    // per-chunk partial images

typedef unsigned long long u64;

__device__ __forceinline__ u64 pk(float lo, float hi) {
    u64 r; asm("mov.b64 %0,{%1,%2};" : "=l"(r) : "f"(lo), "f"(hi)); return r;
}
__device__ __forceinline__ void unpk(u64 v, float& lo, float& hi) {
    asm("mov.b64 {%0,%1},%2;" : "=f"(lo), "=f"(hi) : "l"(v));
}
__device__ __forceinline__ u64 fma2(u64 a, u64 b, u64 c) {
    u64 d; asm("fma.rn.f32x2 %0,%1,%2,%3;" : "=l"(d) : "l"(a), "l"(b), "l"(c)); return d;
}
__device__ __forceinline__ u64 mul2(u64 a, u64 b) {
    u64 d; asm("mul.rn.f32x2 %0,%1,%2;" : "=l"(d) : "l"(a), "l"(b)); return d;
}
__device__ __forceinline__ float ex2n(float t) {   // 2^-t
    float r, nt = -t;
    asm("ex2.approx.ftz.f32 %0,%1;" : "=f"(r) : "f"(nt));
    return r;
}
__device__ __forceinline__ float ndc(int k, int n) {
    return -1.0f + 2.0f * k / (float)(n - 1);
}

// ---------------------------------------------------------------------------
// Prep: fold rotation/scale/center/alpha; compute cull radius.
// weight = 2^-(u'^2+v'^2), rows prescaled by SF = sqrt(0.5*log2(e)).
// Cutoff: w < 1e-7  <=>  dist^2 > 2*ln(1e7)*max(sx,sy)^2.
// ---------------------------------------------------------------------------
__global__ void prep_kernel(const float* __restrict__ pos,
                            const float* __restrict__ colr,
                            const float* __restrict__ lsc,
                            const float* __restrict__ rot,
                            const float* __restrict__ alph,
                            const int*   __restrict__ pnum,
                            int N)
{
    int g = blockIdx.x * blockDim.x + threadIdx.x;
    if (g >= N || g >= MAXN) return;
    int na = pnum ? *pnum : N;

    float gx = pos[2*g], gy = pos[2*g+1];
    float sx = expf(lsc[2*g])   + 1e-6f;
    float sy = expf(lsc[2*g+1]) + 1e-6f;
    float r  = rot[g];
    float c  = cosf(r), s = sinf(r);

    const float SF = 0.8493218002880191f;   // sqrt(0.5*log2(e))
    float isx = SF / sx, isy = SF / sy;
    float m00 =  c * isx, m01 = s * isx;
    float m10 = -s * isy, m11 = c * isy;
    float bu  = -(gx*m00 + gy*m01);
    float bv  = -(gx*m10 + gy*m11);

    float a  = (g < na) ? alph[g] : 0.0f;
    float cr = a * colr[3*g], cg = a * colr[3*g+1], cb = a * colr[3*g+2];

    float mx = fmaxf(sx, sy);
    float rmax2 = (a != 0.0f) ? 32.2362f * mx * mx : -1.0f;  // 2*ln(1e7)

    d_gA[g] = make_float4(m00, m01, m10, m11);
    d_gB[g] = make_float4(bu, bv, cr, cg);
    d_gC[g] = cb;
    d_gP[g] = make_float4(gx, gy, rmax2, 0.0f);
}

// ---------------------------------------------------------------------------
// Binning: one block per tile; ordered (deterministic) compaction of
// intersecting gaussian indices via ballot + block scan.
// ---------------------------------------------------------------------------
__global__ void __launch_bounds__(256)
bin_kernel(int N, int W, int H, int tilesX)
{
    const int tile = blockIdx.x;
    const int tX = tile % tilesX, tY = tile / tilesX;
    const int tid = threadIdx.x;
    const int lane = tid & 31, w = tid >> 5;

    int cx1 = tX*16 + 15; if (cx1 > W-1) cx1 = W-1;
    int cy1 = tY*16 + 15; if (cy1 > H-1) cy1 = H-1;
    const float x0 = ndc(tX*16, W), x1 = ndc(cx1, W);
    const float y0 = ndc(tY*16, H), y1 = ndc(cy1, H);

    __shared__ int wcnt[8], woff[8], scount, stotal;
    if (tid == 0) scount = 0;
    __syncthreads();

    for (int base = 0; base < N; base += 256) {
        int g = base + tid;
        bool pred = false;
        if (g < N) {
            float4 P = d_gP[g];
            float dx = fmaxf(0.0f, fmaxf(x0 - P.x, P.x - x1));
            float dy = fmaxf(0.0f, fmaxf(y0 - P.y, P.y - y1));
            pred = (dx*dx + dy*dy) <= P.z;
        }
        unsigned m = __ballot_sync(0xffffffffu, pred);
        if (lane == 0) wcnt[w] = __popc(m);
        __syncthreads();
        if (tid == 0) {
            int s = 0;
            for (int i = 0; i < 8; i++) { woff[i] = s; s += wcnt[i]; }
            stotal = s;
        }
        __syncthreads();
        if (pred) {
            int p = scount + woff[w] + __popc(m & ((1u << lane) - 1));
            d_list[tile * MAXN + p] = g;
        }
        __syncthreads();
        if (tid == 0) scount += stotal;
        __syncthreads();
    }
    if (tid == 0) d_count[tile] = scount;
}

// ---------------------------------------------------------------------------
// Splat: block = (tile, chunk). 128 threads = 16 cols x 8 row-pairs (f32x2).
// Each block processes its slice of the tile's gaussian list and writes its
// partial for ALL 256 tile pixels (zeros if slice empty) -> deterministic.
// ---------------------------------------------------------------------------
__global__ void __launch_bounds__(128, 8)
splat_kernel(int W, int H, int HW, int tilesX)
{
    __shared__ ulonglong2 sM[128];   // {m01|m01, m11|m11}
    __shared__ ulonglong2 sC[128];   // {cr|cr,  cg|cg}
    __shared__ u64        sB[128];   // cb|cb
    __shared__ float4     sS[128];   // {m00, m10, bu, bv}

    const int tile  = blockIdx.x;
    const int chunk = blockIdx.y;
    const int tX = tile % tilesX, tY = tile / tilesX;
    const int tid  = threadIdx.x;
    const int cidx = tid & 15;       // column in tile
    const int rp   = tid >> 4;       // row pair in tile (0..7)

    const int col  = tX * 16 + cidx;
    const int row0 = tY * 16 + 2 * rp;
    const int row1 = row0 + 1;

    const float px = ndc(col < W ? col : W - 1, W);
    const float y0 = ndc(row0 < H ? row0 : H - 1, H);
    const float y1 = ndc(row1 < H ? row1 : H - 1, H);
    const u64 py2 = pk(y0, y1);

    u64 aR = 0ull, aG = 0ull, aB = 0ull;

    const int len = d_count[tile];
    const int csz = (len + CHUNKS - 1) / CHUNKS;
    const int start = chunk * csz;
    int end = start + csz; if (end > len) end = len;
    const int* list = d_list + tile * MAXN;

    for (int base = start; base < end; base += 128) {
        int li = base + tid;
        if (li < end) {
            int g = list[li];
            float4 A = d_gA[g];
            float4 B = d_gB[g];
            float  c = d_gC[g];
            sM[tid] = make_ulonglong2(pk(A.y, A.y), pk(A.w, A.w));
            sC[tid] = make_ulonglong2(pk(B.z, B.z), pk(B.w, B.w));
            sB[tid] = pk(c, c);
            sS[tid] = make_float4(A.x, A.z, B.x, B.y);
        }
        __syncthreads();

        int cnt = end - base; if (cnt > 128) cnt = 128;
#pragma unroll 2
        for (int j = 0; j < cnt; j++) {
            ulonglong2 M = sM[j];
            ulonglong2 C = sC[j];
            u64       cb = sB[j];
            float4     S = sS[j];
            float cu = fmaf(px, S.x, S.z);
            float cv = fmaf(px, S.y, S.w);
            u64 u  = fma2(py2, M.x, pk(cu, cu));
            u64 v  = fma2(py2, M.y, pk(cv, cv));
            u64 t  = fma2(v, v, mul2(u, u));
            float t0, t1; unpk(t, t0, t1);
            u64 e01 = pk(ex2n(t0), ex2n(t1));
            aR = fma2(e01, C.x, aR);
            aG = fma2(e01, C.y, aG);
            aB = fma2(e01, cb,  aB);
        }
        __syncthreads();
    }

    // always store (zeros included) -> every (chunk, pixel) written exactly once
    float r0, r1, g0, g1, b0, b1;
    unpk(aR, r0, r1); unpk(aG, g0, g1); unpk(aB, b0, b1);
    float* basep = d_partial + (size_t)chunk * 3 * HW;
    if (col < W) {
        if (row0 < H) {
            int pix = row0 * W + col;
            basep[0*HW + pix] = r0; basep[1*HW + pix] = g0; basep[2*HW + pix] = b0;
        }
        if (row1 < H) {
            int pix = row1 * W + col;
            basep[0*HW + pix] = r1; basep[1*HW + pix] = g1; basep[2*HW + pix] = b1;
        }
    }
}

// ---------------------------------------------------------------------------
// Reduce CHUNKS partials (L2-resident, compile-time unrolled -> full MLP),
// subtract 1.
// ---------------------------------------------------------------------------
__global__ void reduce_kernel(float* __restrict__ out, int total)
{
    int i = blockIdx.x * blockDim.x + threadIdx.x;
    if (i >= total) return;
    float s = -1.0f;
#pragma unroll
    for (int k = 0; k < CHUNKS; k++)
        s += d_partial[(size_t)k * total + i];
    out[i] = s;
}

extern "C" void kernel_launch(void* const* d_in, const int* in_sizes, int n_in,
                              void* d_out, int out_size)
{
    const float* pos  = (const float*)d_in[0];   // [1,N,2]
    const float* col  = (const float*)d_in[1];   // [1,N,3]
    const float* lsc  = (const float*)d_in[2];   // [1,N,2]
    const float* rot  = (const float*)d_in[3];   // [1,N]
    const float* alph = (const float*)d_in[4];   // [1,N]
    const int*   pnum = (n_in > 7) ? (const int*)d_in[7] : nullptr;

    int N  = in_sizes[0] / 2;
    if (N > MAXN) N = MAXN;
    int HW = out_size / 3;
    int W  = (int)(sqrt((double)HW) + 0.5);
    int H  = HW / W;
    float* out = (float*)d_out;

    int tilesX = (W + 15) / 16;
    int tilesY = (H + 15) / 16;
    int tiles  = tilesX * tilesY;          // 64 for 128x128
    if (tiles > TCAP) tiles = TCAP;        // (shapes are fixed; defensive)

    prep_kernel<<<(N + 127) / 128, 128>>>(pos, col, lsc, rot, alph, pnum, N);
    bin_kernel<<<tiles, 256>>>(N, W, H, tilesX);

    dim3 grid(tiles, CHUNKS);
    splat_kernel<<<grid, 128>>>(W, H, HW, tilesX);

    reduce_kernel<<<(out_size + 255) / 256, 256>>>(out, out_size);
}